// round 2
// baseline (speedup 1.0000x reference)
#include <cuda_runtime.h>
#include <cstdint>

#define N_NODES   131072
#define N_EDGES   2097152
#define RANK      256
#define L_FLOW    128
#define BATCH     1024          // N_NODES / L_FLOW
#define N_CLASSES 32
#define ORDER     3
#define BN_EPS    1e-5f

// ---------------------------------------------------------------------------
// Scratch (static device globals; no runtime allocation allowed)
// ---------------------------------------------------------------------------
__device__ float g_bufA[(size_t)N_NODES * RANK];   // 128 MiB
__device__ float g_bufB[(size_t)N_NODES * RANK];   // 128 MiB
__device__ float g_ro[BATCH * RANK * ORDER];       // 3 MiB readouts
__device__ float g_stats[2 * RANK];                // column sum / sumsq

// 128-bit global reduction (sm_90+): 4x fewer atomic ops than scalar atomicAdd
__device__ __forceinline__ void red_add_v4(float* p, float4 v) {
    asm volatile("red.global.add.v4.f32 [%0], {%1, %2, %3, %4};"
                 :: "l"(p), "f"(v.x), "f"(v.y), "f"(v.z), "f"(v.w)
                 : "memory");
}

// ---------------------------------------------------------------------------
// 1) seq encoder: feats[n, r] = node_vals[n] * seq_W[r] + seq_b[r]
// ---------------------------------------------------------------------------
__global__ void encode_kernel(const float* __restrict__ nv,
                              const float* __restrict__ sW,
                              const float* __restrict__ sb,
                              float* __restrict__ out) {
    const size_t total = (size_t)N_NODES * (RANK / 4);
    for (size_t idx = (size_t)blockIdx.x * blockDim.x + threadIdx.x;
         idx < total; idx += (size_t)gridDim.x * blockDim.x) {
        size_t n = idx >> 6;           // RANK/4 == 64 float4 per row
        int    q = (int)(idx & 63);
        float  x = __ldg(nv + n);
        float4 w = __ldg((const float4*)sW + q);
        float4 b = __ldg((const float4*)sb + q);
        float4 o;
        o.x = fmaf(x, w.x, b.x);
        o.y = fmaf(x, w.y, b.y);
        o.z = fmaf(x, w.z, b.z);
        o.w = fmaf(x, w.w, b.w);
        ((float4*)out)[idx] = o;
    }
}

// ---------------------------------------------------------------------------
// 2) copy (self term of GIN sum) : dst = src
// ---------------------------------------------------------------------------
__global__ void copy_kernel(const float4* __restrict__ src, float4* __restrict__ dst) {
    const size_t total = (size_t)N_NODES * (RANK / 4);
    for (size_t i = (size_t)blockIdx.x * blockDim.x + threadIdx.x;
         i < total; i += (size_t)gridDim.x * blockDim.x)
        dst[i] = src[i];
}

// ---------------------------------------------------------------------------
// 3) edge scatter: agg[dst] += feats[src].  Warp per edge, 2 x v4 red per lane.
//    256 edges staged in smem per block for coalesced index loads.
//    NOTE: edge indices are int32 (JAX x64 disabled downgrades int64->int32).
// ---------------------------------------------------------------------------
__global__ void scatter_kernel(const float* __restrict__ feats,
                               float* __restrict__ agg,
                               const int* __restrict__ es,
                               const int* __restrict__ ed) {
    __shared__ int ss[256];
    __shared__ int sd[256];
    const int tid  = threadIdx.x;
    const int base = blockIdx.x * 256;
    ss[tid] = es[base + tid];
    sd[tid] = ed[base + tid];
    __syncthreads();

    const int lane = tid & 31;
    const int w    = tid >> 5;          // 8 warps
    #pragma unroll 4
    for (int e = w; e < 256; e += 8) {
        const float4* sp = (const float4*)(feats + (size_t)ss[e] * RANK);
        float*        dp = agg + (size_t)sd[e] * RANK;
        float4 v0 = sp[lane];
        float4 v1 = sp[lane + 32];
        red_add_v4(dp + lane * 4,        v0);
        red_add_v4(dp + 128 + lane * 4,  v1);
    }
}

// ---------------------------------------------------------------------------
// 4) GEMM + bias + ReLU:  Y = relu(X @ W + b)
//    M=131072, N=256, K=256.  128x128 block tile, 8x8 per thread, K-step 16.
// ---------------------------------------------------------------------------
__global__ void __launch_bounds__(256, 2)
gemm_relu_kernel(const float* __restrict__ X, const float* __restrict__ W,
                 const float* __restrict__ bias, float* __restrict__ Y) {
    __shared__ float As[16][132];   // A transposed: As[k][row]
    __shared__ float Bs[16][132];   // Bs[k][col]

    const int tid  = threadIdx.x;
    const int row0 = blockIdx.x * 128;
    const int col0 = blockIdx.y * 128;
    const int ty   = tid >> 4;      // 0..15
    const int tx   = tid & 15;      // 0..15

    float acc[8][8];
    #pragma unroll
    for (int i = 0; i < 8; i++)
        #pragma unroll
        for (int j = 0; j < 8; j++) acc[i][j] = 0.f;

    for (int k0 = 0; k0 < RANK; k0 += 16) {
        #pragma unroll
        for (int l = 0; l < 2; l++) {
            int idx = tid + l * 256;
            // A tile: 128 rows x 16 k
            int r = idx >> 2, q = idx & 3;
            float4 a = *(const float4*)(X + (size_t)(row0 + r) * RANK + k0 + q * 4);
            As[q * 4 + 0][r] = a.x;
            As[q * 4 + 1][r] = a.y;
            As[q * 4 + 2][r] = a.z;
            As[q * 4 + 3][r] = a.w;
            // B tile: 16 k x 128 cols
            int kk = idx >> 5, c4 = idx & 31;
            float4 b = *(const float4*)(W + (size_t)(k0 + kk) * RANK + col0 + c4 * 4);
            *(float4*)&Bs[kk][c4 * 4] = b;
        }
        __syncthreads();

        #pragma unroll
        for (int kk = 0; kk < 16; kk++) {
            float4 a0 = *(const float4*)&As[kk][ty * 8];
            float4 a1 = *(const float4*)&As[kk][ty * 8 + 4];
            float4 b0 = *(const float4*)&Bs[kk][tx * 8];
            float4 b1 = *(const float4*)&Bs[kk][tx * 8 + 4];
            float av[8] = {a0.x, a0.y, a0.z, a0.w, a1.x, a1.y, a1.z, a1.w};
            float bv[8] = {b0.x, b0.y, b0.z, b0.w, b1.x, b1.y, b1.z, b1.w};
            #pragma unroll
            for (int i = 0; i < 8; i++)
                #pragma unroll
                for (int j = 0; j < 8; j++)
                    acc[i][j] = fmaf(av[i], bv[j], acc[i][j]);
        }
        __syncthreads();
    }

    float bj[8];
    #pragma unroll
    for (int j = 0; j < 8; j++) bj[j] = __ldg(bias + col0 + tx * 8 + j);

    #pragma unroll
    for (int i = 0; i < 8; i++) {
        size_t r = (size_t)(row0 + ty * 8 + i);
        #pragma unroll
        for (int j = 0; j < 8; j += 4) {
            float4 o;
            o.x = fmaxf(acc[i][j + 0] + bj[j + 0], 0.f);
            o.y = fmaxf(acc[i][j + 1] + bj[j + 1], 0.f);
            o.z = fmaxf(acc[i][j + 2] + bj[j + 2], 0.f);
            o.w = fmaxf(acc[i][j + 3] + bj[j + 3], 0.f);
            *(float4*)(Y + r * RANK + col0 + tx * 8 + j) = o;
        }
    }
}

// ---------------------------------------------------------------------------
// 5) BN batch stats: per-column sum & sumsq (block = 128-row strip)
// ---------------------------------------------------------------------------
__global__ void zero_stats_kernel(float* __restrict__ stats) {
    stats[threadIdx.x] = 0.f;   // 512 threads
}

__global__ void stats_kernel(const float* __restrict__ Y, float* __restrict__ stats) {
    const int col = threadIdx.x;                    // 256
    const size_t row0 = (size_t)blockIdx.x * 128;
    const float* p = Y + row0 * RANK + col;
    float s = 0.f, s2 = 0.f;
    #pragma unroll 8
    for (int l = 0; l < 128; l++) {
        float v = p[(size_t)l * RANK];
        s += v;
        s2 = fmaf(v, v, s2);
    }
    atomicAdd(&stats[col], s);
    atomicAdd(&stats[RANK + col], s2);
}

// ---------------------------------------------------------------------------
// 6) BN normalize in place: y = (y - mean) * gamma * rsqrt(var+eps) + beta
// ---------------------------------------------------------------------------
__global__ void bn_norm_kernel(float* __restrict__ Y, const float* __restrict__ stats,
                               const float* __restrict__ gamma,
                               const float* __restrict__ beta) {
    const int col = threadIdx.x;
    const float inv = 1.0f / (float)N_NODES;
    float m = stats[col] * inv;
    float v = fmaf(-m, m, stats[RANK + col] * inv);
    float a  = gamma[col] * rsqrtf(v + BN_EPS);
    float bb = fmaf(-m, a, beta[col]);
    for (size_t r = blockIdx.x; r < N_NODES; r += gridDim.x) {
        size_t o = r * RANK + col;
        Y[o] = fmaf(Y[o], a, bb);
    }
}

// ---------------------------------------------------------------------------
// 7) readout: ro[b, layer*256 + r] = sum over the flow's 128 rows
// ---------------------------------------------------------------------------
__global__ void readout_kernel(const float* __restrict__ f, float* __restrict__ ro,
                               int layer) {
    const int b = blockIdx.x;       // 1024
    const int r = threadIdx.x;      // 256
    const float* base = f + (size_t)b * L_FLOW * RANK + r;
    float s = 0.f;
    #pragma unroll 8
    for (int l = 0; l < L_FLOW; l++) s += base[(size_t)l * RANK];
    ro[(size_t)b * (RANK * ORDER) + layer * RANK + r] = s;
}

// ---------------------------------------------------------------------------
// 8) classifier: out[b, c] = ro[b, :] @ clf_W[:, c] + clf_b[c]
// ---------------------------------------------------------------------------
__global__ void classifier_kernel(const float* __restrict__ ro,
                                  const float* __restrict__ W,
                                  const float* __restrict__ b,
                                  float* __restrict__ out) {
    const int bi = blockIdx.x;      // 1024
    const int c  = threadIdx.x;     // 32
    const float* r = ro + (size_t)bi * (RANK * ORDER);
    float acc = b[c];
    #pragma unroll 8
    for (int k = 0; k < RANK * ORDER; k++)
        acc = fmaf(r[k], W[(size_t)k * N_CLASSES + c], acc);
    out[(size_t)bi * N_CLASSES + c] = acc;
}

// ---------------------------------------------------------------------------
// Host driver (graph-capturable: kernel launches only)
// ---------------------------------------------------------------------------
extern "C" void kernel_launch(void* const* d_in, const int* in_sizes, int n_in,
                              void* d_out, int out_size) {
    const float* node_vals = (const float*)d_in[0];
    const int*   edge_src  = (const int*)d_in[1];   // int32 (JAX x64 off)
    const int*   edge_dst  = (const int*)d_in[2];   // int32
    const float* seq_W     = (const float*)d_in[3];
    const float* seq_b     = (const float*)d_in[4];
    const float* mlp_W     = (const float*)d_in[5];   // [3][3][256][256]
    const float* mlp_b     = (const float*)d_in[6];   // [3][3][256]
    const float* bn_gamma  = (const float*)d_in[7];   // [3][3][256]
    const float* bn_beta   = (const float*)d_in[8];   // [3][3][256]
    const float* clf_W     = (const float*)d_in[9];   // [768][32]
    const float* clf_b     = (const float*)d_in[10];  // [32]
    float*       out       = (float*)d_out;

    float *bufA, *bufB, *ro, *stats;
    cudaGetSymbolAddress((void**)&bufA,  g_bufA);
    cudaGetSymbolAddress((void**)&bufB,  g_bufB);
    cudaGetSymbolAddress((void**)&ro,    g_ro);
    cudaGetSymbolAddress((void**)&stats, g_stats);

    // feats -> bufA
    encode_kernel<<<8192, 256>>>(node_vals, seq_W, seq_b, bufA);

    float* fcur = bufA;   // feats live here at top of each layer
    float* faux = bufB;

    const dim3 gemm_grid(N_NODES / 128, RANK / 128);

    for (int i = 0; i < ORDER; i++) {
        // GIN aggregation: faux = fcur + scatter_sum(fcur)
        copy_kernel<<<8192, 256>>>((const float4*)fcur, (float4*)faux);
        scatter_kernel<<<N_EDGES / 256, 256>>>(fcur, faux, edge_src, edge_dst);

        // MLP: 3 x (Linear -> ReLU -> BN).  Ping-pong faux <-> fcur; after an
        // odd number of GEMMs the result lands back in fcur.
        float* Xp = faux;
        float* Yp = fcur;
        for (int j = 0; j < 3; j++) {
            const int s = i * 3 + j;
            zero_stats_kernel<<<1, 2 * RANK>>>(stats);
            gemm_relu_kernel<<<gemm_grid, 256>>>(Xp,
                                                 mlp_W + (size_t)s * RANK * RANK,
                                                 mlp_b + (size_t)s * RANK, Yp);
            stats_kernel<<<N_NODES / 128, RANK>>>(Yp, stats);
            bn_norm_kernel<<<8192, RANK>>>(Yp, stats,
                                           bn_gamma + (size_t)s * RANK,
                                           bn_beta  + (size_t)s * RANK);
            float* t = Xp; Xp = Yp; Yp = t;
        }
        // feats now in fcur (== Xp after 3 swaps)

        readout_kernel<<<BATCH, RANK>>>(fcur, ro, i);
    }

    classifier_kernel<<<BATCH, N_CLASSES>>>(ro, clf_W, clf_b, out);
}

// round 5
// speedup vs baseline: 1.3212x; 1.3212x over previous
#include <cuda_runtime.h>
#include <cuda_bf16.h>
#include <cstdint>

#define N_NODES   131072
#define N_EDGES   2097152
#define RANK      256
#define L_FLOW    128
#define BATCH     1024
#define N_CLASSES 32
#define ORDER     3
#define BN_EPS    1e-5f

// ---------------------------------------------------------------------------
// Scratch (static device globals)
// ---------------------------------------------------------------------------
__device__ float g_bufA[(size_t)N_NODES * RANK];
__device__ float g_bufB[(size_t)N_NODES * RANK];
__device__ float g_ro[BATCH * RANK * ORDER];
__device__ float g_stats[2 * RANK];             // col sum / sumsq
__device__ float g_affine[2 * RANK];            // a / bb (pending BN affine)
__device__ __nv_bfloat16 g_Wh[9 * RANK * RANK]; // Wt hi  [s][out][k]
__device__ __nv_bfloat16 g_Wm[9 * RANK * RANK]; // Wt mid
__device__ __nv_bfloat16 g_Wl[9 * RANK * RANK]; // Wt lo

// 128-bit global reduction
__device__ __forceinline__ void red_add_v4(float* p, float4 v) {
    asm volatile("red.global.add.v4.f32 [%0], {%1, %2, %3, %4};"
                 :: "l"(p), "f"(v.x), "f"(v.y), "f"(v.z), "f"(v.w) : "memory");
}

__device__ __forceinline__ uint32_t smem_u32(const void* p) {
    uint32_t a;
    asm("{ .reg .u64 t; cvta.to.shared.u64 t, %1; cvt.u32.u64 %0, t; }"
        : "=r"(a) : "l"(p));
    return a;
}

__device__ __forceinline__ void ldsm_x4(uint32_t* r, uint32_t addr) {
    asm volatile("ldmatrix.sync.aligned.m8n8.x4.shared.b16 {%0,%1,%2,%3}, [%4];"
                 : "=r"(r[0]), "=r"(r[1]), "=r"(r[2]), "=r"(r[3]) : "r"(addr));
}

__device__ __forceinline__ void mma_bf16(float* c, const uint32_t* a,
                                         uint32_t b0, uint32_t b1) {
    asm volatile(
        "mma.sync.aligned.m16n8k16.row.col.f32.bf16.bf16.f32 "
        "{%0,%1,%2,%3}, {%4,%5,%6,%7}, {%8,%9}, {%0,%1,%2,%3};"
        : "+f"(c[0]), "+f"(c[1]), "+f"(c[2]), "+f"(c[3])
        : "r"(a[0]), "r"(a[1]), "r"(a[2]), "r"(a[3]), "r"(b0), "r"(b1));
}

__device__ __forceinline__ uint32_t pack_bf16x2(float a, float b) {
    __nv_bfloat162 p = __nv_bfloat162(__float2bfloat16(a), __float2bfloat16(b));
    return *(uint32_t*)&p;
}

// ---------------------------------------------------------------------------
// 0) weight prep: Wt 3-term bf16 split, Wt[s][out][k] = W[s][k][out]
// ---------------------------------------------------------------------------
__global__ void prep_w_kernel(const float* __restrict__ W,
                              __nv_bfloat16* __restrict__ Wh,
                              __nv_bfloat16* __restrict__ Wm,
                              __nv_bfloat16* __restrict__ Wl) {
    const int s = blockIdx.x >> 8;
    const int k = blockIdx.x & 255;
    const int out = threadIdx.x;
    float w = W[((size_t)s * 256 + k) * 256 + out];
    __nv_bfloat16 hi = __float2bfloat16(w);
    float r1 = w - __bfloat162float(hi);
    __nv_bfloat16 mi = __float2bfloat16(r1);
    __nv_bfloat16 lo = __float2bfloat16(r1 - __bfloat162float(mi));
    size_t o = ((size_t)s * 256 + out) * 256 + k;
    Wh[o] = hi;
    Wm[o] = mi;
    Wl[o] = lo;
}

// ---------------------------------------------------------------------------
// 1) seq encoder -> both buffers
// ---------------------------------------------------------------------------
__global__ void encode_kernel(const float* __restrict__ nv,
                              const float* __restrict__ sW,
                              const float* __restrict__ sb,
                              float* __restrict__ o1, float* __restrict__ o2) {
    const size_t total = (size_t)N_NODES * (RANK / 4);
    for (size_t idx = (size_t)blockIdx.x * blockDim.x + threadIdx.x;
         idx < total; idx += (size_t)gridDim.x * blockDim.x) {
        size_t n = idx >> 6;
        int    q = (int)(idx & 63);
        float  x = __ldg(nv + n);
        float4 w = __ldg((const float4*)sW + q);
        float4 b = __ldg((const float4*)sb + q);
        float4 o;
        o.x = fmaf(x, w.x, b.x);
        o.y = fmaf(x, w.y, b.y);
        o.z = fmaf(x, w.z, b.z);
        o.w = fmaf(x, w.w, b.w);
        ((float4*)o1)[idx] = o;
        ((float4*)o2)[idx] = o;
    }
}

// ---------------------------------------------------------------------------
// 2) edge scatter: agg[dst] += feats[src]
// ---------------------------------------------------------------------------
__global__ void scatter_kernel(const float* __restrict__ feats,
                               float* __restrict__ agg,
                               const int* __restrict__ es,
                               const int* __restrict__ ed) {
    __shared__ int ss[256];
    __shared__ int sd[256];
    const int tid  = threadIdx.x;
    const int base = blockIdx.x * 256;
    ss[tid] = es[base + tid];
    sd[tid] = ed[base + tid];
    __syncthreads();

    const int lane = tid & 31;
    const int w    = tid >> 5;
    #pragma unroll 4
    for (int e = w; e < 256; e += 8) {
        const float4* sp = (const float4*)(feats + (size_t)ss[e] * RANK);
        float*        dp = agg + (size_t)sd[e] * RANK;
        float4 v0 = sp[lane];
        float4 v1 = sp[lane + 32];
        red_add_v4(dp + lane * 4,       v0);
        red_add_v4(dp + 128 + lane * 4, v1);
    }
}

// ---------------------------------------------------------------------------
// 3) mma.sync GEMM: Y = relu( (X*a + bb) @ W + bias ), fused BN-stats.
//    CTA: 128 x-rows x 128 out features.  Warp grid 4(m) x 2(n).
//    3-term bf16 split (h/m/l) on both operands, 6 products -> ~fp32 accuracy.
//    K processed in 8 chunks of 32.
// ---------------------------------------------------------------------------
#define TS        80                    // smem row stride (bytes): 32 bf16 + pad
#define TILE      (128 * TS)            // 10240
#define AFF_OFF   0
#define XH_OFF    2048
#define XM_OFF    (XH_OFF + TILE)
#define XL_OFF    (XM_OFF + TILE)
#define WH_OFF    (XL_OFF + TILE)
#define WM_OFF    (WH_OFF + TILE)
#define WL_OFF    (WM_OFF + TILE)
#define GEMM_SMEM (WL_OFF + TILE)       // 63488
#define SPLIT_D   TILE                  // delta between h->m, m->l tiles

__global__ void __launch_bounds__(256, 2)
gemm_tc_kernel(const float* __restrict__ X, const float* __restrict__ affine,
               const __nv_bfloat16* __restrict__ Wg_h,
               const __nv_bfloat16* __restrict__ Wg_m,
               const __nv_bfloat16* __restrict__ Wg_l,
               const float* __restrict__ bias, float* __restrict__ Y,
               float* __restrict__ stats) {
    extern __shared__ char smem[];
    const uint32_t sbase = smem_u32(smem);
    const int tid  = threadIdx.x;
    const int wid  = tid >> 5;
    const int lane = tid & 31;
    const int wm   = wid & 3;
    const int wn   = wid >> 2;
    const int x0      = blockIdx.x * 128;
    const int outbase = blockIdx.y * 128;

    float* aff = (float*)(smem + AFF_OFF);
    aff[tid]       = affine[tid];
    aff[256 + tid] = affine[256 + tid];
    __syncthreads();

    float acc[2][8][4];
    #pragma unroll
    for (int mi = 0; mi < 2; mi++)
        #pragma unroll
        for (int nt = 0; nt < 8; nt++)
            #pragma unroll
            for (int e = 0; e < 4; e++) acc[mi][nt][e] = 0.f;

    // ldmatrix base addresses (within the hi tiles; m/l via +SPLIT_D)
    const uint32_t aA = sbase + XH_OFF + (uint32_t)(wm * 32 + (lane & 15)) * TS
                        + ((uint32_t)(lane >> 4) << 4);
    const uint32_t aB = sbase + WH_OFF
                        + (uint32_t)(wn * 64 + ((lane >> 4) << 3) + (lane & 7)) * TS
                        + (((uint32_t)(lane >> 3) & 1) << 4);

    const int lr = tid >> 1;            // row (0..127)
    const int lh = (tid & 1) * 16;      // k sub-offset (0 or 16 floats)

    #pragma unroll 1
    for (int c = 0; c < 8; c++) {
        const int k0 = c * 32;
        if (c) __syncthreads();

        // --- X load + affine + 3-term split ---
        {
            const float4* xs = (const float4*)(X + (size_t)(x0 + lr) * RANK + k0 + lh);
            char* dh = smem + XH_OFF + lr * TS + lh * 2;
            #pragma unroll
            for (int i = 0; i < 4; i++) {
                float4 xv = xs[i];
                const int kg = k0 + lh + i * 4;
                float v0 = fmaf(xv.x, aff[kg + 0], aff[256 + kg + 0]);
                float v1 = fmaf(xv.y, aff[kg + 1], aff[256 + kg + 1]);
                float v2 = fmaf(xv.z, aff[kg + 2], aff[256 + kg + 2]);
                float v3 = fmaf(xv.w, aff[kg + 3], aff[256 + kg + 3]);
                float h0f = __bfloat162float(__float2bfloat16(v0));
                float h1f = __bfloat162float(__float2bfloat16(v1));
                float h2f = __bfloat162float(__float2bfloat16(v2));
                float h3f = __bfloat162float(__float2bfloat16(v3));
                float r0 = v0 - h0f, r1 = v1 - h1f, r2 = v2 - h2f, r3 = v3 - h3f;
                float m0f = __bfloat162float(__float2bfloat16(r0));
                float m1f = __bfloat162float(__float2bfloat16(r1));
                float m2f = __bfloat162float(__float2bfloat16(r2));
                float m3f = __bfloat162float(__float2bfloat16(r3));
                ((uint32_t*)(dh + i * 8))[0] = pack_bf16x2(h0f, h1f);
                ((uint32_t*)(dh + i * 8))[1] = pack_bf16x2(h2f, h3f);
                ((uint32_t*)(dh + SPLIT_D + i * 8))[0] = pack_bf16x2(m0f, m1f);
                ((uint32_t*)(dh + SPLIT_D + i * 8))[1] = pack_bf16x2(m2f, m3f);
                ((uint32_t*)(dh + 2 * SPLIT_D + i * 8))[0] =
                    pack_bf16x2(r0 - m0f, r1 - m1f);
                ((uint32_t*)(dh + 2 * SPLIT_D + i * 8))[1] =
                    pack_bf16x2(r2 - m2f, r3 - m3f);
            }
        }
        // --- W h/m/l load (bf16, [out][k]) : 16 bf16 = 2 uint4 per tile ---
        {
            const size_t go = (size_t)(outbase + lr) * RANK + k0 + lh;
            uint4* dh = (uint4*)(smem + WH_OFF + lr * TS + lh * 2);
            uint4* dm = (uint4*)(smem + WM_OFF + lr * TS + lh * 2);
            uint4* dl = (uint4*)(smem + WL_OFF + lr * TS + lh * 2);
            #pragma unroll
            for (int i = 0; i < 2; i++) {
                dh[i] = ((const uint4*)(Wg_h + go))[i];
                dm[i] = ((const uint4*)(Wg_m + go))[i];
                dl[i] = ((const uint4*)(Wg_l + go))[i];
            }
        }
        __syncthreads();

        // --- MMA: 2 k16 steps x 6 products ---
        #pragma unroll
        for (int t = 0; t < 2; t++) {
            uint32_t ah[2][4], am[2][4], al[2][4];
            const uint32_t aAt = aA + t * 32;
            ldsm_x4(ah[0], aAt);
            ldsm_x4(ah[1], aAt + 16 * TS);
            ldsm_x4(am[0], aAt + SPLIT_D);
            ldsm_x4(am[1], aAt + SPLIT_D + 16 * TS);
            ldsm_x4(al[0], aAt + 2 * SPLIT_D);
            ldsm_x4(al[1], aAt + 2 * SPLIT_D + 16 * TS);
            const uint32_t aBt = aB + t * 32;
            #pragma unroll
            for (int g = 0; g < 4; g++) {
                uint32_t bh[4], bm[4], bl[4];
                ldsm_x4(bh, aBt + g * 16 * TS);
                ldsm_x4(bm, aBt + g * 16 * TS + SPLIT_D);
                ldsm_x4(bl, aBt + g * 16 * TS + 2 * SPLIT_D);
                #pragma unroll
                for (int mi = 0; mi < 2; mi++) {
                    #pragma unroll
                    for (int s = 0; s < 2; s++) {
                        float* cc = acc[mi][g * 2 + s];
                        mma_bf16(cc, ah[mi], bh[2 * s], bh[2 * s + 1]);
                        mma_bf16(cc, ah[mi], bm[2 * s], bm[2 * s + 1]);
                        mma_bf16(cc, am[mi], bh[2 * s], bh[2 * s + 1]);
                        mma_bf16(cc, am[mi], bm[2 * s], bm[2 * s + 1]);
                        mma_bf16(cc, ah[mi], bl[2 * s], bl[2 * s + 1]);
                        mma_bf16(cc, al[mi], bh[2 * s], bh[2 * s + 1]);
                    }
                }
            }
        }
    }

    // --- epilogue: bias + relu + store + fused BN stats ---
    const int gid = lane >> 2, tig = lane & 3;
    float ssum[8][2], ssq[8][2];
    #pragma unroll
    for (int nt = 0; nt < 8; nt++) {
        const int out = outbase + wn * 64 + nt * 8 + 2 * tig;
        const float bv0 = __ldg(bias + out);
        const float bv1 = __ldg(bias + out + 1);
        float s0 = 0.f, s1 = 0.f, q0 = 0.f, q1 = 0.f;
        #pragma unroll
        for (int mi = 0; mi < 2; mi++) {
            const float* cc = acc[mi][nt];
            const int row = x0 + wm * 32 + mi * 16 + gid;
            float v00 = fmaxf(cc[0] + bv0, 0.f);
            float v01 = fmaxf(cc[1] + bv1, 0.f);
            float v10 = fmaxf(cc[2] + bv0, 0.f);
            float v11 = fmaxf(cc[3] + bv1, 0.f);
            *(float2*)(Y + (size_t)row * RANK + out)       = make_float2(v00, v01);
            *(float2*)(Y + (size_t)(row + 8) * RANK + out) = make_float2(v10, v11);
            s0 += v00 + v10;
            s1 += v01 + v11;
            q0 += v00 * v00 + v10 * v10;
            q1 += v01 * v01 + v11 * v11;
        }
        ssum[nt][0] = s0; ssum[nt][1] = s1;
        ssq[nt][0]  = q0; ssq[nt][1]  = q1;
    }
    #pragma unroll
    for (int nt = 0; nt < 8; nt++)
        #pragma unroll
        for (int e = 0; e < 2; e++) {
            float s = ssum[nt][e], q = ssq[nt][e];
            #pragma unroll
            for (int m = 4; m < 32; m <<= 1) {
                s += __shfl_xor_sync(0xFFFFFFFF, s, m);
                q += __shfl_xor_sync(0xFFFFFFFF, q, m);
            }
            ssum[nt][e] = s; ssq[nt][e] = q;
        }
    if (lane < 4) {
        #pragma unroll
        for (int nt = 0; nt < 8; nt++) {
            const int out = outbase + wn * 64 + nt * 8 + 2 * tig;
            atomicAdd(&stats[out],            ssum[nt][0]);
            atomicAdd(&stats[out + 1],        ssum[nt][1]);
            atomicAdd(&stats[RANK + out],     ssq[nt][0]);
            atomicAdd(&stats[RANK + out + 1], ssq[nt][1]);
        }
    }
}

// ---------------------------------------------------------------------------
// 4) affine update: stats -> (a, bb), then zero stats
// ---------------------------------------------------------------------------
__global__ void affine_update_kernel(float* __restrict__ stats,
                                     float* __restrict__ aff,
                                     const float* __restrict__ gamma,
                                     const float* __restrict__ beta) {
    const int c = threadIdx.x;
    const float inv = 1.0f / (float)N_NODES;
    float m   = stats[c] * inv;
    float var = fmaf(-m, m, stats[RANK + c] * inv);
    float a   = gamma[c] * rsqrtf(var + BN_EPS);
    aff[c]        = a;
    aff[RANK + c] = fmaf(-m, a, beta[c]);
    stats[c]        = 0.f;
    stats[RANK + c] = 0.f;
}

__global__ void reset_kernel(float* __restrict__ stats, float* __restrict__ aff) {
    const int c = threadIdx.x;
    aff[c]          = 1.f;
    aff[RANK + c]   = 0.f;
    stats[c]        = 0.f;
    stats[RANK + c] = 0.f;
}

// ---------------------------------------------------------------------------
// 5) finalize: apply BN affine, dual-write feats, per-flow readout
// ---------------------------------------------------------------------------
__global__ void finalize_kernel(const float* __restrict__ Y,
                                const float* __restrict__ aff,
                                float* __restrict__ o1, float* __restrict__ o2,
                                float* __restrict__ ro, int layer) {
    const int b = blockIdx.x;
    const int c = threadIdx.x;
    const float a  = aff[c];
    const float bb = aff[RANK + c];
    float s = 0.f;
    #pragma unroll 8
    for (int r = 0; r < L_FLOW; r++) {
        size_t idx = ((size_t)b * L_FLOW + r) * RANK + c;
        float v = fmaf(Y[idx], a, bb);
        o1[idx] = v;
        o2[idx] = v;
        s += v;
    }
    ro[(size_t)b * (RANK * ORDER) + layer * RANK + c] = s;
}

// ---------------------------------------------------------------------------
// 6) classifier
// ---------------------------------------------------------------------------
__global__ void classifier_kernel(const float* __restrict__ ro,
                                  const float* __restrict__ W,
                                  const float* __restrict__ b,
                                  float* __restrict__ out) {
    const int bi = blockIdx.x;
    const int c  = threadIdx.x;
    const float* r = ro + (size_t)bi * (RANK * ORDER);
    float acc = b[c];
    #pragma unroll 8
    for (int k = 0; k < RANK * ORDER; k++)
        acc = fmaf(r[k], W[(size_t)k * N_CLASSES + c], acc);
    out[(size_t)bi * N_CLASSES + c] = acc;
}

// ---------------------------------------------------------------------------
// Host driver
// ---------------------------------------------------------------------------
extern "C" void kernel_launch(void* const* d_in, const int* in_sizes, int n_in,
                              void* d_out, int out_size) {
    const float* node_vals = (const float*)d_in[0];
    const int*   edge_src  = (const int*)d_in[1];
    const int*   edge_dst  = (const int*)d_in[2];
    const float* seq_W     = (const float*)d_in[3];
    const float* seq_b     = (const float*)d_in[4];
    const float* mlp_W     = (const float*)d_in[5];
    const float* mlp_b     = (const float*)d_in[6];
    const float* bn_gamma  = (const float*)d_in[7];
    const float* bn_beta   = (const float*)d_in[8];
    const float* clf_W     = (const float*)d_in[9];
    const float* clf_b     = (const float*)d_in[10];
    float*       out       = (float*)d_out;

    float *bufA, *bufB, *ro, *stats, *affine;
    __nv_bfloat16 *Wh, *Wm, *Wl;
    cudaGetSymbolAddress((void**)&bufA,   g_bufA);
    cudaGetSymbolAddress((void**)&bufB,   g_bufB);
    cudaGetSymbolAddress((void**)&ro,     g_ro);
    cudaGetSymbolAddress((void**)&stats,  g_stats);
    cudaGetSymbolAddress((void**)&affine, g_affine);
    cudaGetSymbolAddress((void**)&Wh,     g_Wh);
    cudaGetSymbolAddress((void**)&Wm,     g_Wm);
    cudaGetSymbolAddress((void**)&Wl,     g_Wl);

    cudaFuncSetAttribute(gemm_tc_kernel,
                         cudaFuncAttributeMaxDynamicSharedMemorySize, GEMM_SMEM);

    prep_w_kernel<<<9 * 256, 256>>>(mlp_W, Wh, Wm, Wl);
    encode_kernel<<<8192, 256>>>(node_vals, seq_W, seq_b, bufA, bufB);

    const dim3 ggrid(N_NODES / 128, 2);

    for (int i = 0; i < ORDER; i++) {
        reset_kernel<<<1, RANK>>>(stats, affine);
        scatter_kernel<<<N_EDGES / 256, 256>>>(bufA, bufB, edge_src, edge_dst);

        const int s0 = i * 3;
        gemm_tc_kernel<<<ggrid, 256, GEMM_SMEM>>>(
            bufB, affine,
            Wh + (size_t)s0 * 65536, Wm + (size_t)s0 * 65536, Wl + (size_t)s0 * 65536,
            mlp_b + (size_t)s0 * RANK, bufA, stats);
        affine_update_kernel<<<1, RANK>>>(stats, affine,
                                          bn_gamma + (size_t)s0 * RANK,
                                          bn_beta  + (size_t)s0 * RANK);
        gemm_tc_kernel<<<ggrid, 256, GEMM_SMEM>>>(
            bufA, affine,
            Wh + (size_t)(s0 + 1) * 65536, Wm + (size_t)(s0 + 1) * 65536,
            Wl + (size_t)(s0 + 1) * 65536,
            mlp_b + (size_t)(s0 + 1) * RANK, bufB, stats);
        affine_update_kernel<<<1, RANK>>>(stats, affine,
                                          bn_gamma + (size_t)(s0 + 1) * RANK,
                                          bn_beta  + (size_t)(s0 + 1) * RANK);
        gemm_tc_kernel<<<ggrid, 256, GEMM_SMEM>>>(
            bufB, affine,
            Wh + (size_t)(s0 + 2) * 65536, Wm + (size_t)(s0 + 2) * 65536,
            Wl + (size_t)(s0 + 2) * 65536,
            mlp_b + (size_t)(s0 + 2) * RANK, bufA, stats);
        affine_update_kernel<<<1, RANK>>>(stats, affine,
                                          bn_gamma + (size_t)(s0 + 2) * RANK,
                                          bn_beta  + (size_t)(s0 + 2) * RANK);

        finalize_kernel<<<BATCH, RANK>>>(bufA, affine, bufA, bufB, ro, i);
    }

    classifier_kernel<<<BATCH, N_CLASSES>>>(ro, clf_W, clf_b, out);
}

// round 6
// speedup vs baseline: 2.0665x; 1.5642x over previous
#include <cuda_runtime.h>
#include <cuda_fp16.h>
#include <cstdint>

#define N_NODES   131072
#define N_EDGES   2097152
#define RANK      256
#define L_FLOW    128
#define BATCH     1024
#define N_CLASSES 32
#define ORDER     3
#define BN_EPS    1e-5f

// ---------------------------------------------------------------------------
// Scratch (static device globals)
// ---------------------------------------------------------------------------
__device__ float g_bufA[(size_t)N_NODES * RANK];
__device__ float g_bufB[(size_t)N_NODES * RANK];
__device__ float g_ro[BATCH * RANK * ORDER];
__device__ float g_stats[2 * RANK];
__device__ float g_affine[2 * RANK];
__device__ __half g_Wh[9 * RANK * RANK];   // Wt hi  [s][out][k]
__device__ __half g_Wm[9 * RANK * RANK];   // Wt lo (fp16 residual)
__device__ int    g_cnt[N_NODES];
__device__ int    g_off[N_NODES];
__device__ int    g_cur[N_NODES];
__device__ int    g_csr[N_EDGES];
__device__ int    g_bsum[256];

__device__ __forceinline__ uint32_t smem_u32(const void* p) {
    uint32_t a;
    asm("{ .reg .u64 t; cvta.to.shared.u64 t, %1; cvt.u32.u64 %0, t; }"
        : "=r"(a) : "l"(p));
    return a;
}

__device__ __forceinline__ void ldsm_x4(uint32_t* r, uint32_t addr) {
    asm volatile("ldmatrix.sync.aligned.m8n8.x4.shared.b16 {%0,%1,%2,%3}, [%4];"
                 : "=r"(r[0]), "=r"(r[1]), "=r"(r[2]), "=r"(r[3]) : "r"(addr));
}

__device__ __forceinline__ void mma_f16(float* c, const uint32_t* a,
                                        uint32_t b0, uint32_t b1) {
    asm volatile(
        "mma.sync.aligned.m16n8k16.row.col.f32.f16.f16.f32 "
        "{%0,%1,%2,%3}, {%4,%5,%6,%7}, {%8,%9}, {%0,%1,%2,%3};"
        : "+f"(c[0]), "+f"(c[1]), "+f"(c[2]), "+f"(c[3])
        : "r"(a[0]), "r"(a[1]), "r"(a[2]), "r"(a[3]), "r"(b0), "r"(b1));
}

__device__ __forceinline__ uint32_t pack_h2(float a, float b) {
    __half2 p = __halves2half2(__float2half_rn(a), __float2half_rn(b));
    return *(uint32_t*)&p;
}

// ---------------------------------------------------------------------------
// 0) weight prep: fp16 2-term split, transposed [s][out][k]
// ---------------------------------------------------------------------------
__global__ void prep_w_kernel(const float* __restrict__ W,
                              __half* __restrict__ Wh, __half* __restrict__ Wm) {
    const int s = blockIdx.x >> 8;
    const int k = blockIdx.x & 255;
    const int out = threadIdx.x;
    float w = W[((size_t)s * 256 + k) * 256 + out];
    __half hi = __float2half_rn(w);
    __half lo = __float2half_rn(w - __half2float(hi));
    size_t o = ((size_t)s * 256 + out) * 256 + k;
    Wh[o] = hi;
    Wm[o] = lo;
}

// ---------------------------------------------------------------------------
// 1) seq encoder -> bufA
// ---------------------------------------------------------------------------
__global__ void encode_kernel(const float* __restrict__ nv,
                              const float* __restrict__ sW,
                              const float* __restrict__ sb,
                              float* __restrict__ o1) {
    const size_t total = (size_t)N_NODES * (RANK / 4);
    for (size_t idx = (size_t)blockIdx.x * blockDim.x + threadIdx.x;
         idx < total; idx += (size_t)gridDim.x * blockDim.x) {
        size_t n = idx >> 6;
        int    q = (int)(idx & 63);
        float  x = __ldg(nv + n);
        float4 w = __ldg((const float4*)sW + q);
        float4 b = __ldg((const float4*)sb + q);
        float4 o;
        o.x = fmaf(x, w.x, b.x);
        o.y = fmaf(x, w.y, b.y);
        o.z = fmaf(x, w.z, b.z);
        o.w = fmaf(x, w.w, b.w);
        ((float4*)o1)[idx] = o;
    }
}

// ---------------------------------------------------------------------------
// 2) CSR build: zero -> hist -> scan (3 phases) -> fill
// ---------------------------------------------------------------------------
__global__ void zero_cnt_kernel(int* __restrict__ cnt) {
    cnt[blockIdx.x * blockDim.x + threadIdx.x] = 0;
}
__global__ void hist_kernel(const int* __restrict__ ed, int* __restrict__ cnt) {
    atomicAdd(&cnt[ed[blockIdx.x * blockDim.x + threadIdx.x]], 1);
}
__global__ void scan1_kernel(const int* __restrict__ cnt, int* __restrict__ bsum) {
    __shared__ int s[512];
    const int t = threadIdx.x;
    s[t] = cnt[blockIdx.x * 512 + t];
    __syncthreads();
    for (int o = 256; o > 0; o >>= 1) {
        if (t < o) s[t] += s[t + o];
        __syncthreads();
    }
    if (t == 0) bsum[blockIdx.x] = s[0];
}
__global__ void scan2_kernel(int* __restrict__ bsum) {
    __shared__ int s[256];
    const int t = threadIdx.x;
    int v = bsum[t];
    s[t] = v;
    __syncthreads();
    for (int o = 1; o < 256; o <<= 1) {
        int add = (t >= o) ? s[t - o] : 0;
        __syncthreads();
        s[t] += add;
        __syncthreads();
    }
    bsum[t] = s[t] - v;   // exclusive
}
__global__ void scan3_kernel(const int* __restrict__ cnt, const int* __restrict__ bsum,
                             int* __restrict__ off, int* __restrict__ cur) {
    __shared__ int s[512];
    const int t = threadIdx.x;
    const int base = blockIdx.x * 512;
    int v = cnt[base + t];
    s[t] = v;
    __syncthreads();
    for (int o = 1; o < 512; o <<= 1) {
        int add = (t >= o) ? s[t - o] : 0;
        __syncthreads();
        s[t] += add;
        __syncthreads();
    }
    int ex = s[t] - v + bsum[blockIdx.x];
    off[base + t] = ex;
    cur[base + t] = ex;
}
__global__ void fill_kernel(const int* __restrict__ es, const int* __restrict__ ed,
                            int* __restrict__ cur, int* __restrict__ csr) {
    const int e = blockIdx.x * blockDim.x + threadIdx.x;
    int p = atomicAdd(&cur[ed[e]], 1);
    csr[p] = es[e];
}

// ---------------------------------------------------------------------------
// 3) gather: agg[n] = feats[n] + sum_{s in csr[n]} feats[s]   (warp per node)
// ---------------------------------------------------------------------------
__global__ void gather_kernel(const float* __restrict__ feats,
                              float* __restrict__ agg,
                              const int* __restrict__ off,
                              const int* __restrict__ cnt,
                              const int* __restrict__ csr) {
    const int node = blockIdx.x * 8 + (threadIdx.x >> 5);
    const int lane = threadIdx.x & 31;
    const float4* self = (const float4*)(feats + (size_t)node * RANK);
    float4 a0 = self[lane];
    float4 a1 = self[lane + 32];
    const int o = off[node];
    const int d = cnt[node];
    for (int j = 0; j < d; j++) {
        const float4* sp = (const float4*)(feats + (size_t)csr[o + j] * RANK);
        float4 v0 = sp[lane];
        float4 v1 = sp[lane + 32];
        a0.x += v0.x; a0.y += v0.y; a0.z += v0.z; a0.w += v0.w;
        a1.x += v1.x; a1.y += v1.y; a1.z += v1.z; a1.w += v1.w;
    }
    float4* dp = (float4*)(agg + (size_t)node * RANK);
    dp[lane]      = a0;
    dp[lane + 32] = a1;
}

// ---------------------------------------------------------------------------
// 4) mma.sync GEMM (fp16 2-term split, 3 products), fused affine-in + BN stats
// ---------------------------------------------------------------------------
#define TS        144
#define TILE      (128 * TS)            // 18432
#define XH_OFF    2048
#define XM_OFF    (XH_OFF + TILE)
#define WH_OFF    (XM_OFF + TILE)
#define WM_OFF    (WH_OFF + TILE)
#define GEMM_SMEM (WM_OFF + TILE)       // 75776
#define SPLIT_D   TILE

__global__ void __launch_bounds__(256, 2)
gemm_tc_kernel(const float* __restrict__ X, const float* __restrict__ affine,
               const __half* __restrict__ Wg_h, const __half* __restrict__ Wg_m,
               const float* __restrict__ bias, float* __restrict__ Y,
               float* __restrict__ stats) {
    extern __shared__ char smem[];
    const uint32_t sbase = smem_u32(smem);
    const int tid  = threadIdx.x;
    const int wid  = tid >> 5;
    const int lane = tid & 31;
    const int wm   = wid & 3;
    const int wn   = wid >> 2;
    const int x0      = blockIdx.x * 128;
    const int outbase = blockIdx.y * 128;

    float* aff = (float*)smem;
    aff[tid]       = affine[tid];
    aff[256 + tid] = affine[256 + tid];
    __syncthreads();

    float acc[2][8][4];
    #pragma unroll
    for (int mi = 0; mi < 2; mi++)
        #pragma unroll
        for (int nt = 0; nt < 8; nt++)
            #pragma unroll
            for (int e = 0; e < 4; e++) acc[mi][nt][e] = 0.f;

    const uint32_t aA = sbase + XH_OFF + (uint32_t)(wm * 32 + (lane & 15)) * TS
                        + ((uint32_t)(lane >> 4) << 4);
    const uint32_t aB = sbase + WH_OFF
                        + (uint32_t)(wn * 64 + ((lane >> 4) << 3) + (lane & 7)) * TS
                        + (((uint32_t)(lane >> 3) & 1) << 4);

    const int lr = tid >> 1;
    const int lh = (tid & 1) * 32;

    #pragma unroll 1
    for (int c = 0; c < 4; c++) {
        const int k0 = c * 64;
        if (c) __syncthreads();

        // --- X load + affine + fp16 split ---
        {
            const float4* xs = (const float4*)(X + (size_t)(x0 + lr) * RANK + k0 + lh);
            char* dh = smem + XH_OFF + lr * TS + lh * 2;
            #pragma unroll
            for (int i = 0; i < 8; i++) {
                float4 xv = xs[i];
                const int kg = k0 + lh + i * 4;
                float v0 = fmaf(xv.x, aff[kg + 0], aff[256 + kg + 0]);
                float v1 = fmaf(xv.y, aff[kg + 1], aff[256 + kg + 1]);
                float v2 = fmaf(xv.z, aff[kg + 2], aff[256 + kg + 2]);
                float v3 = fmaf(xv.w, aff[kg + 3], aff[256 + kg + 3]);
                float h0 = __half2float(__float2half_rn(v0));
                float h1 = __half2float(__float2half_rn(v1));
                float h2 = __half2float(__float2half_rn(v2));
                float h3 = __half2float(__float2half_rn(v3));
                ((uint32_t*)(dh + i * 8))[0] = pack_h2(h0, h1);
                ((uint32_t*)(dh + i * 8))[1] = pack_h2(h2, h3);
                ((uint32_t*)(dh + SPLIT_D + i * 8))[0] = pack_h2(v0 - h0, v1 - h1);
                ((uint32_t*)(dh + SPLIT_D + i * 8))[1] = pack_h2(v2 - h2, v3 - h3);
            }
        }
        // --- W h/m load (fp16, [out][k]): 32 halves = 4 uint4 per tile ---
        {
            const size_t go = (size_t)(outbase + lr) * RANK + k0 + lh;
            uint4* dh = (uint4*)(smem + WH_OFF + lr * TS + lh * 2);
            uint4* dm = (uint4*)(smem + WM_OFF + lr * TS + lh * 2);
            #pragma unroll
            for (int i = 0; i < 4; i++) {
                dh[i] = ((const uint4*)(Wg_h + go))[i];
                dm[i] = ((const uint4*)(Wg_m + go))[i];
            }
        }
        __syncthreads();

        // --- MMA: 4 k16 steps x 3 products ---
        #pragma unroll
        for (int t = 0; t < 4; t++) {
            uint32_t ah[2][4], am[2][4];
            const uint32_t aAt = aA + t * 32;
            ldsm_x4(ah[0], aAt);
            ldsm_x4(ah[1], aAt + 16 * TS);
            ldsm_x4(am[0], aAt + SPLIT_D);
            ldsm_x4(am[1], aAt + SPLIT_D + 16 * TS);
            const uint32_t aBt = aB + t * 32;
            #pragma unroll
            for (int g = 0; g < 4; g++) {
                uint32_t bh[4], bm[4];
                ldsm_x4(bh, aBt + g * 16 * TS);
                ldsm_x4(bm, aBt + g * 16 * TS + SPLIT_D);
                #pragma unroll
                for (int mi = 0; mi < 2; mi++) {
                    #pragma unroll
                    for (int s = 0; s < 2; s++) {
                        float* cc = acc[mi][g * 2 + s];
                        mma_f16(cc, ah[mi], bh[2 * s], bh[2 * s + 1]);
                        mma_f16(cc, ah[mi], bm[2 * s], bm[2 * s + 1]);
                        mma_f16(cc, am[mi], bh[2 * s], bh[2 * s + 1]);
                    }
                }
            }
        }
    }

    // --- epilogue: bias + relu + store + fused BN stats ---
    const int gid = lane >> 2, tig = lane & 3;
    float ssum[8][2], ssq[8][2];
    #pragma unroll
    for (int nt = 0; nt < 8; nt++) {
        const int out = outbase + wn * 64 + nt * 8 + 2 * tig;
        const float bv0 = __ldg(bias + out);
        const float bv1 = __ldg(bias + out + 1);
        float s0 = 0.f, s1 = 0.f, q0 = 0.f, q1 = 0.f;
        #pragma unroll
        for (int mi = 0; mi < 2; mi++) {
            const float* cc = acc[mi][nt];
            const int row = x0 + wm * 32 + mi * 16 + gid;
            float v00 = fmaxf(cc[0] + bv0, 0.f);
            float v01 = fmaxf(cc[1] + bv1, 0.f);
            float v10 = fmaxf(cc[2] + bv0, 0.f);
            float v11 = fmaxf(cc[3] + bv1, 0.f);
            *(float2*)(Y + (size_t)row * RANK + out)       = make_float2(v00, v01);
            *(float2*)(Y + (size_t)(row + 8) * RANK + out) = make_float2(v10, v11);
            s0 += v00 + v10;
            s1 += v01 + v11;
            q0 += v00 * v00 + v10 * v10;
            q1 += v01 * v01 + v11 * v11;
        }
        ssum[nt][0] = s0; ssum[nt][1] = s1;
        ssq[nt][0]  = q0; ssq[nt][1]  = q1;
    }
    #pragma unroll
    for (int nt = 0; nt < 8; nt++)
        #pragma unroll
        for (int e = 0; e < 2; e++) {
            float s = ssum[nt][e], q = ssq[nt][e];
            #pragma unroll
            for (int m = 4; m < 32; m <<= 1) {
                s += __shfl_xor_sync(0xFFFFFFFF, s, m);
                q += __shfl_xor_sync(0xFFFFFFFF, q, m);
            }
            ssum[nt][e] = s; ssq[nt][e] = q;
        }
    if (lane < 4) {
        #pragma unroll
        for (int nt = 0; nt < 8; nt++) {
            const int out = outbase + wn * 64 + nt * 8 + 2 * tig;
            atomicAdd(&stats[out],            ssum[nt][0]);
            atomicAdd(&stats[out + 1],        ssum[nt][1]);
            atomicAdd(&stats[RANK + out],     ssq[nt][0]);
            atomicAdd(&stats[RANK + out + 1], ssq[nt][1]);
        }
    }
}

// ---------------------------------------------------------------------------
// 5) affine update / reset
// ---------------------------------------------------------------------------
__global__ void affine_update_kernel(float* __restrict__ stats,
                                     float* __restrict__ aff,
                                     const float* __restrict__ gamma,
                                     const float* __restrict__ beta) {
    const int c = threadIdx.x;
    const float inv = 1.0f / (float)N_NODES;
    float m   = stats[c] * inv;
    float var = fmaf(-m, m, stats[RANK + c] * inv);
    float a   = gamma[c] * rsqrtf(var + BN_EPS);
    aff[c]        = a;
    aff[RANK + c] = fmaf(-m, a, beta[c]);
    stats[c]        = 0.f;
    stats[RANK + c] = 0.f;
}

__global__ void reset_kernel(float* __restrict__ stats, float* __restrict__ aff) {
    const int c = threadIdx.x;
    aff[c]          = 1.f;
    aff[RANK + c]   = 0.f;
    stats[c]        = 0.f;
    stats[RANK + c] = 0.f;
}

// ---------------------------------------------------------------------------
// 6) finalize: apply BN affine in place + per-flow readout
// ---------------------------------------------------------------------------
__global__ void finalize_kernel(float* __restrict__ Y, const float* __restrict__ aff,
                                float* __restrict__ ro, int layer) {
    const int b = blockIdx.x;
    const int c = threadIdx.x;
    const float a  = aff[c];
    const float bb = aff[RANK + c];
    float s = 0.f;
    #pragma unroll 8
    for (int r = 0; r < L_FLOW; r++) {
        size_t idx = ((size_t)b * L_FLOW + r) * RANK + c;
        float v = fmaf(Y[idx], a, bb);
        Y[idx] = v;
        s += v;
    }
    ro[(size_t)b * (RANK * ORDER) + layer * RANK + c] = s;
}

// ---------------------------------------------------------------------------
// 7) classifier
// ---------------------------------------------------------------------------
__global__ void classifier_kernel(const float* __restrict__ ro,
                                  const float* __restrict__ W,
                                  const float* __restrict__ b,
                                  float* __restrict__ out) {
    const int bi = blockIdx.x;
    const int c  = threadIdx.x;
    const float* r = ro + (size_t)bi * (RANK * ORDER);
    float acc = b[c];
    #pragma unroll 8
    for (int k = 0; k < RANK * ORDER; k++)
        acc = fmaf(r[k], W[(size_t)k * N_CLASSES + c], acc);
    out[(size_t)bi * N_CLASSES + c] = acc;
}

// ---------------------------------------------------------------------------
// Host driver
// ---------------------------------------------------------------------------
extern "C" void kernel_launch(void* const* d_in, const int* in_sizes, int n_in,
                              void* d_out, int out_size) {
    const float* node_vals = (const float*)d_in[0];
    const int*   edge_src  = (const int*)d_in[1];
    const int*   edge_dst  = (const int*)d_in[2];
    const float* seq_W     = (const float*)d_in[3];
    const float* seq_b     = (const float*)d_in[4];
    const float* mlp_W     = (const float*)d_in[5];
    const float* mlp_b     = (const float*)d_in[6];
    const float* bn_gamma  = (const float*)d_in[7];
    const float* bn_beta   = (const float*)d_in[8];
    const float* clf_W     = (const float*)d_in[9];
    const float* clf_b     = (const float*)d_in[10];
    float*       out       = (float*)d_out;

    float *bufA, *bufB, *ro, *stats, *affine;
    __half *Wh, *Wm;
    int *cnt, *off, *cur, *csr, *bsum;
    cudaGetSymbolAddress((void**)&bufA,   g_bufA);
    cudaGetSymbolAddress((void**)&bufB,   g_bufB);
    cudaGetSymbolAddress((void**)&ro,     g_ro);
    cudaGetSymbolAddress((void**)&stats,  g_stats);
    cudaGetSymbolAddress((void**)&affine, g_affine);
    cudaGetSymbolAddress((void**)&Wh,     g_Wh);
    cudaGetSymbolAddress((void**)&Wm,     g_Wm);
    cudaGetSymbolAddress((void**)&cnt,    g_cnt);
    cudaGetSymbolAddress((void**)&off,    g_off);
    cudaGetSymbolAddress((void**)&cur,    g_cur);
    cudaGetSymbolAddress((void**)&csr,    g_csr);
    cudaGetSymbolAddress((void**)&bsum,   g_bsum);

    cudaFuncSetAttribute(gemm_tc_kernel,
                         cudaFuncAttributeMaxDynamicSharedMemorySize, GEMM_SMEM);

    prep_w_kernel<<<9 * 256, 256>>>(mlp_W, Wh, Wm);
    encode_kernel<<<8192, 256>>>(node_vals, seq_W, seq_b, bufA);

    // CSR build
    zero_cnt_kernel<<<N_NODES / 256, 256>>>(cnt);
    hist_kernel<<<N_EDGES / 512, 512>>>(edge_dst, cnt);
    scan1_kernel<<<256, 512>>>(cnt, bsum);
    scan2_kernel<<<1, 256>>>(bsum);
    scan3_kernel<<<256, 512>>>(cnt, bsum, off, cur);
    fill_kernel<<<N_EDGES / 512, 512>>>(edge_src, edge_dst, cur, csr);

    const dim3 ggrid(N_NODES / 128, 2);

    for (int i = 0; i < ORDER; i++) {
        reset_kernel<<<1, RANK>>>(stats, affine);
        gather_kernel<<<N_NODES / 8, 256>>>(bufA, bufB, off, cnt, csr);

        const int s0 = i * 3;
        gemm_tc_kernel<<<ggrid, 256, GEMM_SMEM>>>(
            bufB, affine, Wh + (size_t)s0 * 65536, Wm + (size_t)s0 * 65536,
            mlp_b + (size_t)s0 * RANK, bufA, stats);
        affine_update_kernel<<<1, RANK>>>(stats, affine,
                                          bn_gamma + (size_t)s0 * RANK,
                                          bn_beta  + (size_t)s0 * RANK);
        gemm_tc_kernel<<<ggrid, 256, GEMM_SMEM>>>(
            bufA, affine, Wh + (size_t)(s0 + 1) * 65536, Wm + (size_t)(s0 + 1) * 65536,
            mlp_b + (size_t)(s0 + 1) * RANK, bufB, stats);
        affine_update_kernel<<<1, RANK>>>(stats, affine,
                                          bn_gamma + (size_t)(s0 + 1) * RANK,
                                          bn_beta  + (size_t)(s0 + 1) * RANK);
        gemm_tc_kernel<<<ggrid, 256, GEMM_SMEM>>>(
            bufB, affine, Wh + (size_t)(s0 + 2) * 65536, Wm + (size_t)(s0 + 2) * 65536,
            mlp_b + (size_t)(s0 + 2) * RANK, bufA, stats);
        affine_update_kernel<<<1, RANK>>>(stats, affine,
                                          bn_gamma + (size_t)(s0 + 2) * RANK,
                                          bn_beta  + (size_t)(s0 + 2) * RANK);

        finalize_kernel<<<BATCH, RANK>>>(bufA, affine, ro, i);
    }

    classifier_kernel<<<BATCH, N_CLASSES>>>(ro, clf_W, clf_b, out);
}

// round 7
// speedup vs baseline: 2.4314x; 1.1766x over previous
#include <cuda_runtime.h>
#include <cuda_fp16.h>
#include <cstdint>

#define N_NODES   131072
#define N_EDGES   2097152
#define RANK      256
#define L_FLOW    128
#define BATCH     1024
#define N_CLASSES 32
#define ORDER     3
#define BN_EPS    1e-5f

// ---------------------------------------------------------------------------
// Scratch
// ---------------------------------------------------------------------------
__device__ __half g_Ah[(size_t)N_NODES * RANK];
__device__ __half g_Al[(size_t)N_NODES * RANK];
__device__ __half g_Bh[(size_t)N_NODES * RANK];
__device__ __half g_Bl[(size_t)N_NODES * RANK];
__device__ __half g_Wph[RANK * RANK];   // folded W' hi [out][k]
__device__ __half g_Wpm[RANK * RANK];   // folded W' lo
__device__ float  g_ro[BATCH * RANK * ORDER];
__device__ float  g_stats[2 * RANK];
__device__ float  g_affine[2 * RANK];   // a / bb
__device__ float  g_cvec[RANK];         // bb^T W
__device__ float  g_degw[N_NODES];      // 1 + in-degree
__device__ int    g_cnt[N_NODES];
__device__ int    g_off[N_NODES];
__device__ int    g_cur[N_NODES];
__device__ int    g_csr[N_EDGES];
__device__ int    g_bsum[256];

__device__ __forceinline__ uint32_t smem_u32(const void* p) {
    uint32_t a;
    asm("{ .reg .u64 t; cvta.to.shared.u64 t, %1; cvt.u32.u64 %0, t; }"
        : "=r"(a) : "l"(p));
    return a;
}
__device__ __forceinline__ void ldsm_x4(uint32_t* r, uint32_t addr) {
    asm volatile("ldmatrix.sync.aligned.m8n8.x4.shared.b16 {%0,%1,%2,%3}, [%4];"
                 : "=r"(r[0]), "=r"(r[1]), "=r"(r[2]), "=r"(r[3]) : "r"(addr));
}
__device__ __forceinline__ void mma_f16(float* c, const uint32_t* a,
                                        uint32_t b0, uint32_t b1) {
    asm volatile(
        "mma.sync.aligned.m16n8k16.row.col.f32.f16.f16.f32 "
        "{%0,%1,%2,%3}, {%4,%5,%6,%7}, {%8,%9}, {%0,%1,%2,%3};"
        : "+f"(c[0]), "+f"(c[1]), "+f"(c[2]), "+f"(c[3])
        : "r"(a[0]), "r"(a[1]), "r"(a[2]), "r"(a[3]), "r"(b0), "r"(b1));
}
__device__ __forceinline__ void cp16(uint32_t s, const void* g) {
    asm volatile("cp.async.cg.shared.global [%0], [%1], 16;"
                 :: "r"(s), "l"(g) : "memory");
}
#define CP_COMMIT() asm volatile("cp.async.commit_group;" ::: "memory")
#define CP_WAIT1()  asm volatile("cp.async.wait_group 1;" ::: "memory")
#define CP_WAIT0()  asm volatile("cp.async.wait_group 0;" ::: "memory")

__device__ __forceinline__ uint32_t pack_h2(float a, float b) {
    __half2 p = __halves2half2(__float2half_rn(a), __float2half_rn(b));
    return *(uint32_t*)&p;
}

// ---------------------------------------------------------------------------
// 1) seq encoder -> split h/l
// ---------------------------------------------------------------------------
__global__ void encode_kernel(const float* __restrict__ nv,
                              const float* __restrict__ sW,
                              const float* __restrict__ sb,
                              __half* __restrict__ Yh, __half* __restrict__ Yl) {
    const size_t total = (size_t)N_NODES * 32;   // 8 feats per thread
    for (size_t idx = (size_t)blockIdx.x * blockDim.x + threadIdx.x;
         idx < total; idx += (size_t)gridDim.x * blockDim.x) {
        size_t n = idx >> 5;
        int    q = (int)(idx & 31);
        float  x = __ldg(nv + n);
        float v[8];
        #pragma unroll
        for (int j = 0; j < 2; j++) {
            float4 w = __ldg((const float4*)sW + q * 2 + j);
            float4 b = __ldg((const float4*)sb + q * 2 + j);
            v[j * 4 + 0] = fmaf(x, w.x, b.x);
            v[j * 4 + 1] = fmaf(x, w.y, b.y);
            v[j * 4 + 2] = fmaf(x, w.z, b.z);
            v[j * 4 + 3] = fmaf(x, w.w, b.w);
        }
        uint4 oh, ol;
        uint32_t* hp = (uint32_t*)&oh;
        uint32_t* lp = (uint32_t*)&ol;
        #pragma unroll
        for (int j = 0; j < 4; j++) {
            float a = v[2 * j], b = v[2 * j + 1];
            float ha = __half2float(__float2half_rn(a));
            float hb = __half2float(__float2half_rn(b));
            hp[j] = pack_h2(ha, hb);
            lp[j] = pack_h2(a - ha, b - hb);
        }
        ((uint4*)(Yh + n * RANK))[q] = oh;
        ((uint4*)(Yl + n * RANK))[q] = ol;
    }
}

// ---------------------------------------------------------------------------
// 2) CSR build
// ---------------------------------------------------------------------------
__global__ void zero_cnt_kernel(int* __restrict__ cnt) {
    cnt[blockIdx.x * blockDim.x + threadIdx.x] = 0;
}
__global__ void hist_kernel(const int* __restrict__ ed, int* __restrict__ cnt) {
    atomicAdd(&cnt[ed[blockIdx.x * blockDim.x + threadIdx.x]], 1);
}
__global__ void scan1_kernel(const int* __restrict__ cnt, int* __restrict__ bsum) {
    __shared__ int s[512];
    const int t = threadIdx.x;
    s[t] = cnt[blockIdx.x * 512 + t];
    __syncthreads();
    for (int o = 256; o > 0; o >>= 1) {
        if (t < o) s[t] += s[t + o];
        __syncthreads();
    }
    if (t == 0) bsum[blockIdx.x] = s[0];
}
__global__ void scan2_kernel(int* __restrict__ bsum) {
    __shared__ int s[256];
    const int t = threadIdx.x;
    int v = bsum[t];
    s[t] = v;
    __syncthreads();
    for (int o = 1; o < 256; o <<= 1) {
        int add = (t >= o) ? s[t - o] : 0;
        __syncthreads();
        s[t] += add;
        __syncthreads();
    }
    bsum[t] = s[t] - v;
}
__global__ void scan3_kernel(const int* __restrict__ cnt, const int* __restrict__ bsum,
                             int* __restrict__ off, int* __restrict__ cur,
                             float* __restrict__ degw) {
    __shared__ int s[512];
    const int t = threadIdx.x;
    const int base = blockIdx.x * 512;
    int v = cnt[base + t];
    s[t] = v;
    __syncthreads();
    for (int o = 1; o < 512; o <<= 1) {
        int add = (t >= o) ? s[t - o] : 0;
        __syncthreads();
        s[t] += add;
        __syncthreads();
    }
    int ex = s[t] - v + bsum[blockIdx.x];
    off[base + t]  = ex;
    cur[base + t]  = ex;
    degw[base + t] = 1.0f + (float)v;
}
__global__ void fill_kernel(const int* __restrict__ es, const int* __restrict__ ed,
                            int* __restrict__ cur, int* __restrict__ csr) {
    const int e = blockIdx.x * blockDim.x + threadIdx.x;
    int p = atomicAdd(&cur[ed[e]], 1);
    csr[p] = es[e];
}

// ---------------------------------------------------------------------------
// 3) gather (raw Y): z = y_self + sum y_neighbors ; write split h/l
// ---------------------------------------------------------------------------
__global__ void gather_kernel(const __half* __restrict__ Yh,
                              const __half* __restrict__ Yl,
                              __half* __restrict__ Zh, __half* __restrict__ Zl,
                              const int* __restrict__ off,
                              const int* __restrict__ cnt,
                              const int* __restrict__ csr) {
    const int node = blockIdx.x * 8 + (threadIdx.x >> 5);
    const int lane = threadIdx.x & 31;
    float acc[8];
    {
        uint4 hv = ((const uint4*)(Yh + (size_t)node * RANK))[lane];
        uint4 lv = ((const uint4*)(Yl + (size_t)node * RANK))[lane];
        const __half2* hp = (const __half2*)&hv;
        const __half2* lp = (const __half2*)&lv;
        #pragma unroll
        for (int j = 0; j < 4; j++) {
            float2 f = __half22float2(hp[j]);
            float2 g = __half22float2(lp[j]);
            acc[2 * j]     = f.x + g.x;
            acc[2 * j + 1] = f.y + g.y;
        }
    }
    const int o = off[node];
    const int d = cnt[node];
    for (int j = 0; j < d; j++) {
        const size_t s = (size_t)csr[o + j] * RANK;
        uint4 hv = ((const uint4*)(Yh + s))[lane];
        uint4 lv = ((const uint4*)(Yl + s))[lane];
        const __half2* hp = (const __half2*)&hv;
        const __half2* lp = (const __half2*)&lv;
        #pragma unroll
        for (int q = 0; q < 4; q++) {
            float2 f = __half22float2(hp[q]);
            float2 g = __half22float2(lp[q]);
            acc[2 * q]     += f.x + g.x;
            acc[2 * q + 1] += f.y + g.y;
        }
    }
    uint4 oh, ol;
    uint32_t* hp = (uint32_t*)&oh;
    uint32_t* lp = (uint32_t*)&ol;
    #pragma unroll
    for (int j = 0; j < 4; j++) {
        float a = acc[2 * j], b = acc[2 * j + 1];
        float ha = __half2float(__float2half_rn(a));
        float hb = __half2float(__float2half_rn(b));
        hp[j] = pack_h2(ha, hb);
        lp[j] = pack_h2(a - ha, b - hb);
    }
    ((uint4*)(Zh + (size_t)node * RANK))[lane] = oh;
    ((uint4*)(Zl + (size_t)node * RANK))[lane] = ol;
}

// ---------------------------------------------------------------------------
// 4) weight fold: W' = diag(a) W (transposed, split), cvec += bb^T W
// ---------------------------------------------------------------------------
__global__ void prep_wfold_kernel(const float* __restrict__ W,
                                  const float* __restrict__ aff,
                                  __half* __restrict__ Wph,
                                  __half* __restrict__ Wpm,
                                  float* __restrict__ cvec) {
    __shared__ float t[32][33];
    __shared__ float cp[32][33];
    const int tx = threadIdx.x, ty = threadIdx.y;
    const int k   = blockIdx.y * 32 + ty;
    const int out = blockIdx.x * 32 + tx;
    float w = W[(size_t)k * RANK + out];
    t[ty][tx]  = w;
    cp[ty][tx] = aff[RANK + k] * w;
    __syncthreads();
    for (int o = 16; o > 0; o >>= 1) {
        if (ty < o) cp[ty][tx] += cp[ty + o][tx];
        __syncthreads();
    }
    if (ty == 0) atomicAdd(&cvec[out], cp[0][tx]);
    // transposed write: out' = bx*32+ty, k' = by*32+tx
    const int kp   = blockIdx.y * 32 + tx;
    const int outp = blockIdx.x * 32 + ty;
    float wv = aff[kp] * t[tx][ty];
    __half h = __float2half_rn(wv);
    __half m = __float2half_rn(wv - __half2float(h));
    Wph[(size_t)outp * RANK + kp] = h;
    Wpm[(size_t)outp * RANK + kp] = m;
}

// ---------------------------------------------------------------------------
// 5) GEMM: Y = relu(X W' + bias + degf*cvec), X/W' fp16 h+l (3 products),
//    2-stage cp.async pipeline, fused BN stats, split h/l output.
// ---------------------------------------------------------------------------
#define TS        80
#define TILE      (128 * TS)            // 10240
#define STAGE     (4 * TILE)            // 40960
#define GEMM_SMEM (2 * STAGE)           // 81920

__global__ void __launch_bounds__(256, 2)
gemm_tc_kernel(const __half* __restrict__ Xh, const __half* __restrict__ Xl,
               const __half* __restrict__ Wph, const __half* __restrict__ Wpm,
               const float* __restrict__ bias, const float* __restrict__ cvec,
               const float* __restrict__ degw,
               __half* __restrict__ Yh, __half* __restrict__ Yl,
               float* __restrict__ stats) {
    extern __shared__ char smem[];
    const uint32_t sbase = smem_u32(smem);
    const int tid  = threadIdx.x;
    const int wid  = tid >> 5;
    const int lane = tid & 31;
    const int wm_  = wid & 3;
    const int wn   = wid >> 2;
    const int outbase = blockIdx.x * 128;   // n-split first -> L2 reuse of X
    const int x0      = blockIdx.y * 128;

    // --- copy-thread mapping: 2 threads per row, 32B each per tile ---
    const int lr  = tid >> 1;
    const int lsb = (tid & 1) * 32;          // byte offset within 64B row
    const int lsh = (tid & 1) * 16;          // halves
    const char* gsrc[4];
    gsrc[0] = (const char*)(Xh  + (size_t)(x0 + lr)      * RANK + lsh);
    gsrc[1] = (const char*)(Xl  + (size_t)(x0 + lr)      * RANK + lsh);
    gsrc[2] = (const char*)(Wph + (size_t)(outbase + lr) * RANK + lsh);
    gsrc[3] = (const char*)(Wpm + (size_t)(outbase + lr) * RANK + lsh);
    uint32_t sdst[4];
    #pragma unroll
    for (int t = 0; t < 4; t++) sdst[t] = sbase + t * TILE + lr * TS + lsb;

    float acc[2][8][4];
    #pragma unroll
    for (int mi = 0; mi < 2; mi++)
        #pragma unroll
        for (int nt = 0; nt < 8; nt++)
            #pragma unroll
            for (int e = 0; e < 4; e++) acc[mi][nt][e] = 0.f;

    const uint32_t aA = sbase + (uint32_t)(wm_ * 32 + (lane & 15)) * TS
                        + ((uint32_t)(lane >> 4) << 4);
    const uint32_t aB = sbase + 2 * TILE
                        + (uint32_t)(wn * 64 + ((lane >> 4) << 3) + (lane & 7)) * TS
                        + (((uint32_t)(lane >> 3) & 1) << 4);

    // prologue: chunk 0
    #pragma unroll
    for (int t = 0; t < 4; t++) {
        cp16(sdst[t],      gsrc[t]);
        cp16(sdst[t] + 16, gsrc[t] + 16);
    }
    CP_COMMIT();

    #pragma unroll 1
    for (int c = 0; c < 8; c++) {
        if (c < 7) {
            const int st = ((c + 1) & 1) * STAGE;
            const int go = (c + 1) * 64;
            #pragma unroll
            for (int t = 0; t < 4; t++) {
                cp16(sdst[t] + st,      gsrc[t] + go);
                cp16(sdst[t] + st + 16, gsrc[t] + go + 16);
            }
            CP_COMMIT();
            CP_WAIT1();
        } else {
            CP_WAIT0();
        }
        __syncthreads();

        const uint32_t st = (uint32_t)((c & 1) * STAGE);
        #pragma unroll
        for (int t = 0; t < 2; t++) {
            uint32_t ah[2][4], am[2][4];
            const uint32_t aAt = aA + st + t * 32;
            ldsm_x4(ah[0], aAt);
            ldsm_x4(ah[1], aAt + 16 * TS);
            ldsm_x4(am[0], aAt + TILE);
            ldsm_x4(am[1], aAt + TILE + 16 * TS);
            const uint32_t aBt = aB + st + t * 32;
            #pragma unroll
            for (int g = 0; g < 4; g++) {
                uint32_t bh[4], bm[4];
                ldsm_x4(bh, aBt + g * 16 * TS);
                ldsm_x4(bm, aBt + g * 16 * TS + TILE);
                #pragma unroll
                for (int mi = 0; mi < 2; mi++) {
                    #pragma unroll
                    for (int s = 0; s < 2; s++) {
                        float* cc = acc[mi][g * 2 + s];
                        mma_f16(cc, ah[mi], bh[2 * s], bh[2 * s + 1]);
                        mma_f16(cc, ah[mi], bm[2 * s], bm[2 * s + 1]);
                        mma_f16(cc, am[mi], bh[2 * s], bh[2 * s + 1]);
                    }
                }
            }
        }
        __syncthreads();
    }

    // --- epilogue ---
    const int gid = lane >> 2, tig = lane & 3;
    float df[4] = {1.f, 1.f, 1.f, 1.f};
    if (degw) {
        const int rb = x0 + wm_ * 32 + gid;
        df[0] = degw[rb];
        df[1] = degw[rb + 8];
        df[2] = degw[rb + 16];
        df[3] = degw[rb + 24];
    }
    float ssum[8][2], ssq[8][2];
    #pragma unroll
    for (int nt = 0; nt < 8; nt++) {
        const int out = outbase + wn * 64 + nt * 8 + 2 * tig;
        const float b0 = __ldg(bias + out),  b1 = __ldg(bias + out + 1);
        const float c0 = __ldg(cvec + out),  c1 = __ldg(cvec + out + 1);
        float s0 = 0.f, s1 = 0.f, q0 = 0.f, q1 = 0.f;
        #pragma unroll
        for (int mi = 0; mi < 2; mi++) {
            const float* cc = acc[mi][nt];
            const int row = x0 + wm_ * 32 + mi * 16 + gid;
            float v00 = fmaxf(cc[0] + b0 + df[2 * mi] * c0, 0.f);
            float v01 = fmaxf(cc[1] + b1 + df[2 * mi] * c1, 0.f);
            float v10 = fmaxf(cc[2] + b0 + df[2 * mi + 1] * c0, 0.f);
            float v11 = fmaxf(cc[3] + b1 + df[2 * mi + 1] * c1, 0.f);
            float h00 = __half2float(__float2half_rn(v00));
            float h01 = __half2float(__float2half_rn(v01));
            float h10 = __half2float(__float2half_rn(v10));
            float h11 = __half2float(__float2half_rn(v11));
            *(uint32_t*)(Yh + (size_t)row * RANK + out)       = pack_h2(h00, h01);
            *(uint32_t*)(Yl + (size_t)row * RANK + out)       = pack_h2(v00 - h00, v01 - h01);
            *(uint32_t*)(Yh + (size_t)(row + 8) * RANK + out) = pack_h2(h10, h11);
            *(uint32_t*)(Yl + (size_t)(row + 8) * RANK + out) = pack_h2(v10 - h10, v11 - h11);
            s0 += v00 + v10;
            s1 += v01 + v11;
            q0 += v00 * v00 + v10 * v10;
            q1 += v01 * v01 + v11 * v11;
        }
        ssum[nt][0] = s0; ssum[nt][1] = s1;
        ssq[nt][0]  = q0; ssq[nt][1]  = q1;
    }
    #pragma unroll
    for (int nt = 0; nt < 8; nt++)
        #pragma unroll
        for (int e = 0; e < 2; e++) {
            float s = ssum[nt][e], q = ssq[nt][e];
            #pragma unroll
            for (int m = 4; m < 32; m <<= 1) {
                s += __shfl_xor_sync(0xFFFFFFFF, s, m);
                q += __shfl_xor_sync(0xFFFFFFFF, q, m);
            }
            ssum[nt][e] = s; ssq[nt][e] = q;
        }
    if (lane < 4) {
        #pragma unroll
        for (int nt = 0; nt < 8; nt++) {
            const int out = outbase + wn * 64 + nt * 8 + 2 * tig;
            atomicAdd(&stats[out],            ssum[nt][0]);
            atomicAdd(&stats[out + 1],        ssum[nt][1]);
            atomicAdd(&stats[RANK + out],     ssq[nt][0]);
            atomicAdd(&stats[RANK + out + 1], ssq[nt][1]);
        }
    }
}

// ---------------------------------------------------------------------------
// 6) affine update / reset (also zero stats + cvec)
// ---------------------------------------------------------------------------
__global__ void affine_update_kernel(float* __restrict__ stats,
                                     float* __restrict__ aff,
                                     float* __restrict__ cvec,
                                     const float* __restrict__ gamma,
                                     const float* __restrict__ beta) {
    const int c = threadIdx.x;
    const float inv = 1.0f / (float)N_NODES;
    float m   = stats[c] * inv;
    float var = fmaf(-m, m, stats[RANK + c] * inv);
    float a   = gamma[c] * rsqrtf(var + BN_EPS);
    aff[c]        = a;
    aff[RANK + c] = fmaf(-m, a, beta[c]);
    stats[c]        = 0.f;
    stats[RANK + c] = 0.f;
    cvec[c]         = 0.f;
}
__global__ void reset_kernel(float* __restrict__ stats, float* __restrict__ aff,
                             float* __restrict__ cvec) {
    const int c = threadIdx.x;
    aff[c]          = 1.f;
    aff[RANK + c]   = 0.f;
    stats[c]        = 0.f;
    stats[RANK + c] = 0.f;
    cvec[c]         = 0.f;
}

// ---------------------------------------------------------------------------
// 7) readout on raw Y: ro = a * S_flow + 128 * bb
// ---------------------------------------------------------------------------
__global__ void readout_kernel(const __half* __restrict__ Yh,
                               const __half* __restrict__ Yl,
                               const float* __restrict__ aff,
                               float* __restrict__ ro, int layer) {
    const int b = blockIdx.x;
    const int c = threadIdx.x;
    float s = 0.f;
    #pragma unroll 8
    for (int r = 0; r < L_FLOW; r++) {
        size_t idx = ((size_t)b * L_FLOW + r) * RANK + c;
        s += __half2float(Yh[idx]) + __half2float(Yl[idx]);
    }
    ro[(size_t)b * (RANK * ORDER) + layer * RANK + c] =
        fmaf(aff[c], s, 128.f * aff[RANK + c]);
}

// ---------------------------------------------------------------------------
// 8) classifier
// ---------------------------------------------------------------------------
__global__ void classifier_kernel(const float* __restrict__ ro,
                                  const float* __restrict__ W,
                                  const float* __restrict__ b,
                                  float* __restrict__ out) {
    const int bi = blockIdx.x;
    const int c  = threadIdx.x;
    const float* r = ro + (size_t)bi * (RANK * ORDER);
    float acc = b[c];
    #pragma unroll 8
    for (int k = 0; k < RANK * ORDER; k++)
        acc = fmaf(r[k], W[(size_t)k * N_CLASSES + c], acc);
    out[(size_t)bi * N_CLASSES + c] = acc;
}

// ---------------------------------------------------------------------------
// Host driver
// ---------------------------------------------------------------------------
extern "C" void kernel_launch(void* const* d_in, const int* in_sizes, int n_in,
                              void* d_out, int out_size) {
    const float* node_vals = (const float*)d_in[0];
    const int*   edge_src  = (const int*)d_in[1];
    const int*   edge_dst  = (const int*)d_in[2];
    const float* seq_W     = (const float*)d_in[3];
    const float* seq_b     = (const float*)d_in[4];
    const float* mlp_W     = (const float*)d_in[5];
    const float* mlp_b     = (const float*)d_in[6];
    const float* bn_gamma  = (const float*)d_in[7];
    const float* bn_beta   = (const float*)d_in[8];
    const float* clf_W     = (const float*)d_in[9];
    const float* clf_b     = (const float*)d_in[10];
    float*       out       = (float*)d_out;

    __half *Ah, *Al, *Bh, *Bl, *Wph, *Wpm;
    float *ro, *stats, *affine, *cvec, *degw;
    int *cnt, *off, *cur, *csr, *bsum;
    cudaGetSymbolAddress((void**)&Ah,     g_Ah);
    cudaGetSymbolAddress((void**)&Al,     g_Al);
    cudaGetSymbolAddress((void**)&Bh,     g_Bh);
    cudaGetSymbolAddress((void**)&Bl,     g_Bl);
    cudaGetSymbolAddress((void**)&Wph,    g_Wph);
    cudaGetSymbolAddress((void**)&Wpm,    g_Wpm);
    cudaGetSymbolAddress((void**)&ro,     g_ro);
    cudaGetSymbolAddress((void**)&stats,  g_stats);
    cudaGetSymbolAddress((void**)&affine, g_affine);
    cudaGetSymbolAddress((void**)&cvec,   g_cvec);
    cudaGetSymbolAddress((void**)&degw,   g_degw);
    cudaGetSymbolAddress((void**)&cnt,    g_cnt);
    cudaGetSymbolAddress((void**)&off,    g_off);
    cudaGetSymbolAddress((void**)&cur,    g_cur);
    cudaGetSymbolAddress((void**)&csr,    g_csr);
    cudaGetSymbolAddress((void**)&bsum,   g_bsum);

    cudaFuncSetAttribute(gemm_tc_kernel,
                         cudaFuncAttributeMaxDynamicSharedMemorySize, GEMM_SMEM);

    encode_kernel<<<4096, 256>>>(node_vals, seq_W, seq_b, Ah, Al);

    zero_cnt_kernel<<<N_NODES / 256, 256>>>(cnt);
    hist_kernel<<<N_EDGES / 512, 512>>>(edge_dst, cnt);
    scan1_kernel<<<256, 512>>>(cnt, bsum);
    scan2_kernel<<<1, 256>>>(bsum);
    scan3_kernel<<<256, 512>>>(cnt, bsum, off, cur, degw);
    fill_kernel<<<N_EDGES / 512, 512>>>(edge_src, edge_dst, cur, csr);

    reset_kernel<<<1, RANK>>>(stats, affine, cvec);

    const dim3 ggrid(2, N_NODES / 128);
    const dim3 pgrid(8, 8);
    const dim3 pblk(32, 32);

    for (int i = 0; i < ORDER; i++) {
        const int s0 = i * 3;
        gather_kernel<<<N_NODES / 8, 256>>>(Ah, Al, Bh, Bl, off, cnt, csr);

        prep_wfold_kernel<<<pgrid, pblk>>>(mlp_W + (size_t)s0 * 65536, affine,
                                           Wph, Wpm, cvec);
        gemm_tc_kernel<<<ggrid, 256, GEMM_SMEM>>>(
            Bh, Bl, Wph, Wpm, mlp_b + (size_t)s0 * RANK, cvec, degw,
            Ah, Al, stats);
        affine_update_kernel<<<1, RANK>>>(stats, affine, cvec,
                                          bn_gamma + (size_t)s0 * RANK,
                                          bn_beta  + (size_t)s0 * RANK);

        prep_wfold_kernel<<<pgrid, pblk>>>(mlp_W + (size_t)(s0 + 1) * 65536, affine,
                                           Wph, Wpm, cvec);
        gemm_tc_kernel<<<ggrid, 256, GEMM_SMEM>>>(
            Ah, Al, Wph, Wpm, mlp_b + (size_t)(s0 + 1) * RANK, cvec, nullptr,
            Bh, Bl, stats);
        affine_update_kernel<<<1, RANK>>>(stats, affine, cvec,
                                          bn_gamma + (size_t)(s0 + 1) * RANK,
                                          bn_beta  + (size_t)(s0 + 1) * RANK);

        prep_wfold_kernel<<<pgrid, pblk>>>(mlp_W + (size_t)(s0 + 2) * 65536, affine,
                                           Wph, Wpm, cvec);
        gemm_tc_kernel<<<ggrid, 256, GEMM_SMEM>>>(
            Bh, Bl, Wph, Wpm, mlp_b + (size_t)(s0 + 2) * RANK, cvec, nullptr,
            Ah, Al, stats);
        affine_update_kernel<<<1, RANK>>>(stats, affine, cvec,
                                          bn_gamma + (size_t)(s0 + 2) * RANK,
                                          bn_beta  + (size_t)(s0 + 2) * RANK);

        readout_kernel<<<BATCH, RANK>>>(Ah, Al, affine, ro, i);
    }

    classifier_kernel<<<BATCH, N_CLASSES>>>(ro, clf_W, clf_b, out);
}